// round 9
// baseline (speedup 1.0000x reference)
#include <cuda_runtime.h>
#include <cuda_fp16.h>
#include <cstdint>
#include <math.h>

// Problem constants: B=2, T=2048, D=1024, F=4096, E=8, TOP_K=2
#define NTOK 4096
#define DIM  1024
#define FDIM 4096
#define NEXP 8

// GEMM tiling: 128x128 CTA tile, 4 warps (2x2), warp tile 64x64, BK=32 (fp16)
#define BM 128
#define BN 128
#define BK 32
#define APITCH 96                          // bytes per A row in smem
#define STAGES 4
#define A_STAGE_BYTES (BM * APITCH)        // 12288
#define B_STAGE_BYTES (BK * BN * 2)        // 8192
#define SMEM_B_OFF (STAGES * A_STAGE_BYTES)                    // 49152
#define SMEM_TOK_OFF (SMEM_B_OFF + STAGES * B_STAGE_BYTES)     // 81920
#define SMEM_W_OFF  (SMEM_TOK_OFF + 512)                       // 82432
#define SMEM_TOTAL  (SMEM_W_OFF + 512)                         // 82944

// ---------------------------------------------------------------------------
// Device-global scratch (no runtime allocation)
// ---------------------------------------------------------------------------
__device__ int    g_cnt[NEXP];
__device__ int    g_tok[NEXP * NTOK];                  // packed tok*2 + slot
__device__ float  g_gw [NEXP * NTOK];
__device__ __half g_h  [(size_t)9216 * FDIM];          // compact h rows, fp16, k-permuted
__device__ __half g_x  [(size_t)NTOK * DIM];           // x, fp16, k-permuted
__device__ __half g_w1p[(size_t)NEXP * DIM * FDIM];    // W1 fragment-packed fp16
__device__ __half g_w2p[(size_t)NEXP * FDIM * DIM];    // W2 fragment-packed fp16
__device__ float  g_y  [(size_t)2 * NTOK * DIM];       // per-slot weighted outputs

// ---------------------------------------------------------------------------
// helpers
// ---------------------------------------------------------------------------
// k-permutation within a 16-block: A-fragment {2t,2t+1,2t+8,2t+9} contiguous.
__device__ __forceinline__ int permh(int j) {
    return ((j & 7) >> 1) * 4 + (j & 1) + ((j >> 3) & 1) * 2;
}
__device__ __forceinline__ uint32_t smem_u32(const void* p) {
    uint32_t a;
    asm("{ .reg .u64 t; cvta.to.shared.u64 t, %1; cvt.u32.u64 %0, t; }" : "=r"(a) : "l"(p));
    return a;
}
__device__ __forceinline__ void mma_f16(float* d, const uint32_t* a, const uint32_t* b) {
    asm volatile(
        "mma.sync.aligned.m16n8k16.row.col.f32.f16.f16.f32 "
        "{%0,%1,%2,%3},{%4,%5,%6,%7},{%8,%9},{%0,%1,%2,%3};"
        : "+f"(d[0]), "+f"(d[1]), "+f"(d[2]), "+f"(d[3])
        : "r"(a[0]), "r"(a[1]), "r"(a[2]), "r"(a[3]),
          "r"(b[0]), "r"(b[1]));
}
#define CP16(dst, src) \
    asm volatile("cp.async.cg.shared.global [%0],[%1],16;" :: "r"(dst), "l"(src) : "memory")
#define CP16Z(dst, src, sz) \
    asm volatile("cp.async.cg.shared.global [%0],[%1],16,%2;" :: "r"(dst), "l"(src), "r"(sz) : "memory")
#define CP_COMMIT() asm volatile("cp.async.commit_group;" ::: "memory")
#define CP_WAIT(n)  asm volatile("cp.async.wait_group %0;" :: "n"(n) : "memory")

// ---------------------------------------------------------------------------
// Pre-convert x: fp32 -> fp16(rn), k-permuted
// ---------------------------------------------------------------------------
__global__ __launch_bounds__(256) void conv_x_kernel(const float* __restrict__ x) {
    int q = blockIdx.x * 256 + threadIdx.x;            // 8 halfs each
    if (q >= NTOK * DIM / 8) return;
    int tok = q >> 7, k0 = (q & 127) * 8;
    const float4 v0 = *(const float4*)(x + (size_t)tok * DIM + k0);
    const float4 v1 = *(const float4*)(x + (size_t)tok * DIM + k0 + 4);
    __half* dst = g_x + (size_t)tok * DIM + (k0 & ~15);
    int b = k0 & 15;
    *(__half2*)(dst + permh(b + 0)) = __floats2half2_rn(v0.x, v0.y);
    *(__half2*)(dst + permh(b + 2)) = __floats2half2_rn(v0.z, v0.w);
    *(__half2*)(dst + permh(b + 4)) = __floats2half2_rn(v1.x, v1.y);
    *(__half2*)(dst + permh(b + 6)) = __floats2half2_rn(v1.z, v1.w);
}

// ---------------------------------------------------------------------------
// Router (packs tok*2+slot); g_cnt zeroed beforehand via cudaMemsetAsync
// ---------------------------------------------------------------------------
__global__ __launch_bounds__(256) void router_kernel(const float* __restrict__ x,
                                                     const float* __restrict__ Wr) {
    __shared__ float sWr[DIM * NEXP];
    const int tid = threadIdx.x;
    for (int i = tid; i < DIM * NEXP; i += 256) sWr[i] = Wr[i];
    __syncthreads();

    const int warp = tid >> 5, lane = tid & 31;
    const int tok = blockIdx.x * 8 + warp;
    const float* xr = x + (size_t)tok * DIM;

    float acc[NEXP];
#pragma unroll
    for (int e = 0; e < NEXP; e++) acc[e] = 0.f;
    for (int d = lane; d < DIM; d += 32) {
        float xv = xr[d];
        const float* wrow = &sWr[d * NEXP];
#pragma unroll
        for (int e = 0; e < NEXP; e++) acc[e] += xv * wrow[e];
    }
#pragma unroll
    for (int e = 0; e < NEXP; e++)
#pragma unroll
        for (int s = 16; s > 0; s >>= 1)
            acc[e] += __shfl_xor_sync(0xFFFFFFFFu, acc[e], s);

    if (lane == 0) {
        int i0 = 0; float v0 = acc[0];
#pragma unroll
        for (int e = 1; e < NEXP; e++) if (acc[e] > v0) { v0 = acc[e]; i0 = e; }
        int i1 = -1; float v1 = -1e30f;
#pragma unroll
        for (int e = 0; e < NEXP; e++) if (e != i0 && acc[e] > v1) { v1 = acc[e]; i1 = e; }
        float r  = expf(v1 - v0);
        float w0 = 1.f / (1.f + r);
        float w1 = r / (1.f + r);
        int p0 = atomicAdd(&g_cnt[i0], 1);
        g_tok[i0 * NTOK + p0] = tok * 2 + 0; g_gw[i0 * NTOK + p0] = w0;
        int p1 = atomicAdd(&g_cnt[i1], 1);
        g_tok[i1 * NTOK + p1] = tok * 2 + 1; g_gw[i1 * NTOK + p1] = w1;
    }
}

// ---------------------------------------------------------------------------
// Pre-convert+pack W — SMEM-free (one thread = one 8B output granule)
// ---------------------------------------------------------------------------
template <int KD, int ND, int NT_, int KIT_>
__global__ __launch_bounds__(256) void conv_w_kernel(const float* __restrict__ W,
                                                     __half* __restrict__ wp) {
    const int e = blockIdx.z, nt = blockIdx.y, kb = blockIdx.x;
    const float* Wt = W + ((size_t)e * KD + kb * 32) * ND + nt * 128;
    uint2* op = (uint2*)(wp + (((size_t)e * NT_ + nt) * KIT_ + kb) * 4096);
    const int tid = threadIdx.x;
#pragma unroll
    for (int p = 0; p < 4; p++) {
        int G = tid + p * 256;               // 0..1023
        int s = G >> 9;
        int r = G & 511;
        int n = (r >> 5) * 8 + ((r & 31) >> 2);
        int t = r & 3;
        int k0 = s * 16 + 2 * t;
        float f0 = Wt[(size_t)(k0    ) * ND + n];
        float f1 = Wt[(size_t)(k0 + 1) * ND + n];
        float f2 = Wt[(size_t)(k0 + 8) * ND + n];
        float f3 = Wt[(size_t)(k0 + 9) * ND + n];
        __half2 h0 = __floats2half2_rn(f0, f1);
        __half2 h1 = __floats2half2_rn(f2, f3);
        uint2 u;
        u.x = *(uint32_t*)&h0;
        u.y = *(uint32_t*)&h1;
        op[G] = u;
    }
}

// ---------------------------------------------------------------------------
// GEMM. G1: h = gelu(x@W1 + b1) -> g_h (fp16, k-permuted).
//       G2: g_y[slot][tok] = gw * (h@W2 + b2).
// Per-k32 iteration: ALL 32 fragment LDS.64 issued first (max MLP), then 64
// MMAs — hides the ~30cyc LDS latency once per iter instead of twice.
// ---------------------------------------------------------------------------
template <bool G1, int KDIM, int NDIM, int NT_>
__global__ __launch_bounds__(128, 2) void moe_gemm_kernel(
    const __half* __restrict__ Bpack,
    const float* __restrict__ bias)
{
    const int e = blockIdx.z;
    // padded prefix offsets computed inline (offsets_kernel removed)
    int off = 0, cnt = 0;
#pragma unroll
    for (int i = 0; i < NEXP; i++) {
        int c = g_cnt[i];
        if (i == e) cnt = c;
        if (i < e) off += (c + 127) & ~127;
    }
    const int mt = blockIdx.y;
    if (mt * BM >= cnt) return;
    const int nt = blockIdx.x;

    extern __shared__ char smem[];
    const uint32_t sA = smem_u32(smem);
    const uint32_t sB = sA + SMEM_B_OFF;
    int*   sTok = (int*)(smem + SMEM_TOK_OFF);
    float* sW   = (float*)(smem + SMEM_W_OFF);

    const int tid  = threadIdx.x;
    const int warp = tid >> 5, lane = tid & 31;
    const int wm = warp >> 1, wn = warp & 1;
    const int gid = lane >> 2, tig = lane & 3;

    if (tid < BM) {
        int slot = mt * BM + tid;
        sTok[tid] = (slot < cnt) ? g_tok[e * NTOK + slot] : -1;
        sW[tid]   = (slot < cnt) ? g_gw [e * NTOK + slot] : 0.f;
    }
    __syncthreads();

    const int hrow0 = off + mt * BM;
    constexpr int KIT = KDIM / BK;

    const __half* srcA[4];
    uint32_t dstA[4], szA[4];
    const int kq = tid & 3;
#pragma unroll
    for (int c = 0; c < 4; c++) {
        int r = (tid >> 2) + c * 32;
        dstA[c] = r * APITCH + kq * 16;
        if constexpr (G1) {
            int tkr = sTok[r];
            int tk  = tkr >> 1;
            srcA[c] = g_x + (size_t)(tkr >= 0 ? tk : 0) * DIM + kq * 8;
            szA[c]  = (tkr >= 0) ? 16u : 0u;
        } else {
            srcA[c] = g_h + (size_t)(hrow0 + r) * KDIM + kq * 8;
            szA[c]  = 16u;
        }
    }
    const __half* srcB = Bpack + (((size_t)e * NT_ + nt) * KIT) * 4096 + tid * 8;

    float acc[4][8][4];
#pragma unroll
    for (int mi = 0; mi < 4; mi++)
#pragma unroll
        for (int ni = 0; ni < 8; ni++)
#pragma unroll
            for (int r = 0; r < 4; r++) acc[mi][ni][r] = 0.f;

    auto FILL = [&](int it, int buf) {
        const uint32_t aB = sA + buf * A_STAGE_BYTES;
        const uint32_t bB = sB + buf * B_STAGE_BYTES;
        const int koff = it * BK;
#pragma unroll
        for (int c = 0; c < 4; c++)
            CP16Z(aB + dstA[c], srcA[c] + koff, szA[c]);
        const __half* bsrc = srcB + (size_t)it * 4096;
#pragma unroll
        for (int c = 0; c < 4; c++)
            CP16(bB + (tid + c * 128) * 16, bsrc + c * 1024);
    };

    auto COMPUTE = [&](int buf) {
        const uint32_t aB = sA + buf * A_STAGE_BYTES;
        const uint32_t bB = sB + buf * B_STAGE_BYTES;
        uint32_t af[2][4][4], bf[2][8][2];
        // batch ALL fragment loads for the k32 iteration
#pragma unroll
        for (int k16 = 0; k16 < 2; k16++) {
#pragma unroll
            for (int mi = 0; mi < 4; mi++) {
                uint32_t ad = aB + (wm * 64 + mi * 16 + gid) * APITCH + k16 * 32 + tig * 8;
                asm("ld.shared.v2.b32 {%0,%1},[%2];"
                    : "=r"(af[k16][mi][0]), "=r"(af[k16][mi][2]) : "r"(ad));
                asm("ld.shared.v2.b32 {%0,%1},[%2];"
                    : "=r"(af[k16][mi][1]), "=r"(af[k16][mi][3]) : "r"(ad + 8 * APITCH));
            }
#pragma unroll
            for (int ni = 0; ni < 8; ni++) {
                uint32_t bd = bB + k16 * 4096 + (wn * 8 + ni) * 256 + lane * 8;
                asm("ld.shared.v2.b32 {%0,%1},[%2];"
                    : "=r"(bf[k16][ni][0]), "=r"(bf[k16][ni][1]) : "r"(bd));
            }
        }
        // then all MMAs
#pragma unroll
        for (int k16 = 0; k16 < 2; k16++)
#pragma unroll
            for (int mi = 0; mi < 4; mi++)
#pragma unroll
                for (int ni = 0; ni < 8; ni++)
                    mma_f16(acc[mi][ni], af[k16][mi], bf[k16][ni]);
    };

#pragma unroll
    for (int s = 0; s < STAGES - 1; s++) { FILL(s, s); CP_COMMIT(); }

#pragma unroll 1
    for (int it = 0; it < KIT; ++it) {
        CP_WAIT(2);
        __syncthreads();
        COMPUTE(it & (STAGES - 1));
        int nf = it + STAGES - 1;
        if (nf < KIT) FILL(nf, nf & (STAGES - 1));
        CP_COMMIT();
    }
    __syncthreads();    // pipeline drained; smem reusable

    // ---- epilogue via SMEM bounce; lane-major coalesced global stores
    if constexpr (G1) {
        __half* sH = (__half*)smem;          // 128 rows x 136 halfs
#pragma unroll
        for (int mi = 0; mi < 4; mi++) {
#pragma unroll
            for (int ni = 0; ni < 8; ni++) {
                int Lb = wn * 64 + ni * 8 + tig * 2;
                float b0 = bias[e * NDIM + nt * BN + Lb];
                float b1 = bias[e * NDIM + nt * BN + Lb + 1];
                int pos = (Lb & ~15) + permh(Lb & 15);
#pragma unroll
                for (int h = 0; h < 2; h++) {
                    int row = wm * 64 + mi * 16 + gid + h * 8;
                    float vx = acc[mi][ni][h * 2 + 0] + b0;
                    float vy = acc[mi][ni][h * 2 + 1] + b1;
                    vx = 0.5f * vx * (1.f + erff(vx * 0.70710678118654752f));
                    vy = 0.5f * vy * (1.f + erff(vy * 0.70710678118654752f));
                    *(__half2*)(sH + row * 136 + pos) = __floats2half2_rn(vx, vy);
                }
            }
        }
        __syncthreads();
#pragma unroll
        for (int i = 0; i < 16; i++) {
            int idx = tid + i * 128;
            int row = idx >> 4, c = idx & 15;
            ((uint4*)(g_h + (size_t)(hrow0 + row) * NDIM + nt * BN))[c]
                = ((const uint4*)(sH + row * 136))[c];
        }
    } else {
        float* sO = (float*)smem;            // 128 rows x 132 words
#pragma unroll
        for (int mi = 0; mi < 4; mi++) {
#pragma unroll
            for (int ni = 0; ni < 8; ni++) {
                int Lb = wn * 64 + ni * 8 + tig * 2;
                float b0 = bias[e * NDIM + nt * BN + Lb];
                float b1 = bias[e * NDIM + nt * BN + Lb + 1];
#pragma unroll
                for (int h = 0; h < 2; h++) {
                    int row = wm * 64 + mi * 16 + gid + h * 8;
                    float w = sW[row];
                    float vx = (acc[mi][ni][h * 2 + 0] + b0) * w;
                    float vy = (acc[mi][ni][h * 2 + 1] + b1) * w;
                    *(float2*)(sO + row * 132 + Lb) = make_float2(vx, vy);
                }
            }
        }
        __syncthreads();
#pragma unroll
        for (int i = 0; i < 32; i++) {
            int idx = tid + i * 128;
            int row = idx >> 5, c = idx & 31;
            int tkr = sTok[row];
            if (tkr >= 0) {
                ((float4*)(g_y + ((size_t)(tkr & 1) * NTOK + (tkr >> 1)) * DIM + nt * BN))[c]
                    = ((const float4*)(sO + row * 132))[c];
            }
        }
    }
}

// ---------------------------------------------------------------------------
// Combine: out = y0 + y1
// ---------------------------------------------------------------------------
__global__ __launch_bounds__(256) void combine_kernel(float4* __restrict__ out4) {
    int i = blockIdx.x * 256 + threadIdx.x;
    if (i >= NTOK * DIM / 4) return;
    const float4 a = ((const float4*)g_y)[i];
    const float4 b = ((const float4*)g_y)[i + NTOK * DIM / 4];
    out4[i] = make_float4(a.x + b.x, a.y + b.y, a.z + b.z, a.w + b.w);
}

// ---------------------------------------------------------------------------
namespace {
cudaStream_t s1;
cudaEvent_t  evF, ev1;
struct ModuleWarmup {
    ModuleWarmup() {
        void* p = nullptr;
        (void)cudaGetSymbolAddress(&p, g_h);
        (void)cudaGetSymbolAddress(&p, g_w1p);
        (void)cudaGetSymbolAddress(&p, g_w2p);
        (void)cudaGetSymbolAddress(&p, g_x);
        (void)cudaGetSymbolAddress(&p, g_y);
        cudaStreamCreateWithFlags(&s1, cudaStreamNonBlocking);
        cudaEventCreateWithFlags(&evF, cudaEventDisableTiming);
        cudaEventCreateWithFlags(&ev1, cudaEventDisableTiming);
    }
};
ModuleWarmup g_module_warmup;
}

extern "C" void kernel_launch(void* const* d_in, const int* in_sizes, int n_in,
                              void* d_out, int out_size) {
    const float* x  = (const float*)d_in[0];   // [2,2048,1024]
    const float* Wr = (const float*)d_in[1];   // [1024,8]
    const float* W1 = (const float*)d_in[2];   // [8,1024,4096]
    const float* b1 = (const float*)d_in[3];   // [8,4096]
    const float* W2 = (const float*)d_in[4];   // [8,4096,1024]
    const float* b2 = (const float*)d_in[5];   // [8,1024]
    float* out = (float*)d_out;                // [2,2048,1024]

    __half *w1p = nullptr, *w2p = nullptr;
    int* cntp = nullptr;
    cudaGetSymbolAddress((void**)&w1p, g_w1p);
    cudaGetSymbolAddress((void**)&w2p, g_w2p);
    cudaGetSymbolAddress((void**)&cntp, g_cnt);

    cudaFuncSetAttribute(moe_gemm_kernel<true,  DIM,  FDIM, 32>,
                         cudaFuncAttributeMaxDynamicSharedMemorySize, SMEM_TOTAL);
    cudaFuncSetAttribute(moe_gemm_kernel<false, FDIM, DIM, 8>,
                         cudaFuncAttributeMaxDynamicSharedMemorySize, SMEM_TOTAL);

    // conv_x concurrent with router (independent); weights serial before G1
    cudaMemsetAsync(cntp, 0, sizeof(int) * NEXP, 0);
    cudaEventRecord(evF, 0);
    cudaStreamWaitEvent(s1, evF, 0);
    conv_x_kernel<<<(NTOK * DIM / 8 + 255) / 256, 256, 0, s1>>>(x);
    cudaEventRecord(ev1, s1);

    router_kernel<<<NTOK / 8, 256>>>(x, Wr);
    conv_w_kernel<DIM,  FDIM, 32, 32 ><<<dim3(32,  32, NEXP), 256>>>(W1, w1p);
    conv_w_kernel<FDIM, DIM,  8,  128><<<dim3(128, 8,  NEXP), 256>>>(W2, w2p);

    cudaStreamWaitEvent(0, ev1, 0);
    {
        dim3 grid(FDIM / BN, NTOK / BM, NEXP);   // (32, 32, 8)
        moe_gemm_kernel<true, DIM, FDIM, 32><<<grid, 128, SMEM_TOTAL>>>(w1p, b1);
    }
    {
        dim3 grid(DIM / BN, NTOK / BM, NEXP);    // (8, 32, 8)
        moe_gemm_kernel<false, FDIM, DIM, 8><<<grid, 128, SMEM_TOTAL>>>(w2p, b2);
    }
    combine_kernel<<<(NTOK * DIM / 4 + 255) / 256, 256>>>((float4*)out);
}

// round 10
// speedup vs baseline: 1.0294x; 1.0294x over previous
#include <cuda_runtime.h>
#include <cuda_fp16.h>
#include <cstdint>
#include <math.h>

// Problem constants: B=2, T=2048, D=1024, F=4096, E=8, TOP_K=2
#define NTOK 4096
#define DIM  1024
#define FDIM 4096
#define NEXP 8

// GEMM tiling: 128x128 CTA tile, 4 warps (2x2), warp tile 64x64, BK=32 (fp16)
#define BM 128
#define BN 128
#define BK 32
#define APITCH 96                          // bytes per A row in smem
#define STAGES 4
#define A_STAGE_BYTES (BM * APITCH)        // 12288
#define B_STAGE_BYTES (BK * BN * 2)        // 8192
#define SMEM_B_OFF (STAGES * A_STAGE_BYTES)                    // 49152
#define SMEM_TOK_OFF (SMEM_B_OFF + STAGES * B_STAGE_BYTES)     // 81920
#define SMEM_W_OFF  (SMEM_TOK_OFF + 512)                       // 82432
#define SMEM_TOTAL  (SMEM_W_OFF + 512)                         // 82944

// ---------------------------------------------------------------------------
// Device-global scratch (no runtime allocation)
// ---------------------------------------------------------------------------
__device__ int    g_cnt[NEXP];
__device__ int    g_tok[NEXP * NTOK];                  // packed tok*2 + slot
__device__ float  g_gw [NEXP * NTOK];
__device__ __half g_h  [(size_t)9216 * FDIM];          // compact h rows, fp16, k-permuted
__device__ __half g_x  [(size_t)NTOK * DIM];           // x, fp16, k-permuted
__device__ __half g_w1p[(size_t)NEXP * DIM * FDIM];    // W1 fragment-packed fp16
__device__ __half g_w2p[(size_t)NEXP * FDIM * DIM];    // W2 fragment-packed fp16
__device__ float  g_y  [(size_t)2 * NTOK * DIM];       // per-slot weighted outputs

// ---------------------------------------------------------------------------
// helpers
// ---------------------------------------------------------------------------
// k-permutation within a 16-block: A-fragment {2t,2t+1,2t+8,2t+9} contiguous.
__device__ __forceinline__ int permh(int j) {
    return ((j & 7) >> 1) * 4 + (j & 1) + ((j >> 3) & 1) * 2;
}
__device__ __forceinline__ uint32_t smem_u32(const void* p) {
    uint32_t a;
    asm("{ .reg .u64 t; cvta.to.shared.u64 t, %1; cvt.u32.u64 %0, t; }" : "=r"(a) : "l"(p));
    return a;
}
__device__ __forceinline__ void mma_f16(float* d, const uint32_t* a, const uint32_t* b) {
    asm volatile(
        "mma.sync.aligned.m16n8k16.row.col.f32.f16.f16.f32 "
        "{%0,%1,%2,%3},{%4,%5,%6,%7},{%8,%9},{%0,%1,%2,%3};"
        : "+f"(d[0]), "+f"(d[1]), "+f"(d[2]), "+f"(d[3])
        : "r"(a[0]), "r"(a[1]), "r"(a[2]), "r"(a[3]),
          "r"(b[0]), "r"(b[1]));
}
#define CP16(dst, src) \
    asm volatile("cp.async.cg.shared.global [%0],[%1],16;" :: "r"(dst), "l"(src) : "memory")
#define CP16Z(dst, src, sz) \
    asm volatile("cp.async.cg.shared.global [%0],[%1],16,%2;" :: "r"(dst), "l"(src), "r"(sz) : "memory")
#define CP_COMMIT() asm volatile("cp.async.commit_group;" ::: "memory")
#define CP_WAIT(n)  asm volatile("cp.async.wait_group %0;" :: "n"(n) : "memory")

// ---------------------------------------------------------------------------
// Pre-convert x: fp32 -> fp16(rn), k-permuted
// ---------------------------------------------------------------------------
__global__ __launch_bounds__(256) void conv_x_kernel(const float* __restrict__ x) {
    int q = blockIdx.x * 256 + threadIdx.x;            // 8 halfs each
    if (q >= NTOK * DIM / 8) return;
    int tok = q >> 7, k0 = (q & 127) * 8;
    const float4 v0 = *(const float4*)(x + (size_t)tok * DIM + k0);
    const float4 v1 = *(const float4*)(x + (size_t)tok * DIM + k0 + 4);
    __half* dst = g_x + (size_t)tok * DIM + (k0 & ~15);
    int b = k0 & 15;
    *(__half2*)(dst + permh(b + 0)) = __floats2half2_rn(v0.x, v0.y);
    *(__half2*)(dst + permh(b + 2)) = __floats2half2_rn(v0.z, v0.w);
    *(__half2*)(dst + permh(b + 4)) = __floats2half2_rn(v1.x, v1.y);
    *(__half2*)(dst + permh(b + 6)) = __floats2half2_rn(v1.z, v1.w);
}

// ---------------------------------------------------------------------------
// Router (packs tok*2+slot); g_cnt zeroed beforehand via cudaMemsetAsync
// ---------------------------------------------------------------------------
__global__ __launch_bounds__(256) void router_kernel(const float* __restrict__ x,
                                                     const float* __restrict__ Wr) {
    __shared__ float sWr[DIM * NEXP];
    const int tid = threadIdx.x;
    for (int i = tid; i < DIM * NEXP; i += 256) sWr[i] = Wr[i];
    __syncthreads();

    const int warp = tid >> 5, lane = tid & 31;
    const int tok = blockIdx.x * 8 + warp;
    const float* xr = x + (size_t)tok * DIM;

    float acc[NEXP];
#pragma unroll
    for (int e = 0; e < NEXP; e++) acc[e] = 0.f;
    for (int d = lane; d < DIM; d += 32) {
        float xv = xr[d];
        const float* wrow = &sWr[d * NEXP];
#pragma unroll
        for (int e = 0; e < NEXP; e++) acc[e] += xv * wrow[e];
    }
#pragma unroll
    for (int e = 0; e < NEXP; e++)
#pragma unroll
        for (int s = 16; s > 0; s >>= 1)
            acc[e] += __shfl_xor_sync(0xFFFFFFFFu, acc[e], s);

    if (lane == 0) {
        int i0 = 0; float v0 = acc[0];
#pragma unroll
        for (int e = 1; e < NEXP; e++) if (acc[e] > v0) { v0 = acc[e]; i0 = e; }
        int i1 = -1; float v1 = -1e30f;
#pragma unroll
        for (int e = 0; e < NEXP; e++) if (e != i0 && acc[e] > v1) { v1 = acc[e]; i1 = e; }
        float r  = expf(v1 - v0);
        float w0 = 1.f / (1.f + r);
        float w1 = r / (1.f + r);
        int p0 = atomicAdd(&g_cnt[i0], 1);
        g_tok[i0 * NTOK + p0] = tok * 2 + 0; g_gw[i0 * NTOK + p0] = w0;
        int p1 = atomicAdd(&g_cnt[i1], 1);
        g_tok[i1 * NTOK + p1] = tok * 2 + 1; g_gw[i1 * NTOK + p1] = w1;
    }
}

// ---------------------------------------------------------------------------
// Pre-convert+pack W — SMEM-free (one thread = one 8B output granule)
// ---------------------------------------------------------------------------
template <int KD, int ND, int NT_, int KIT_>
__global__ __launch_bounds__(256) void conv_w_kernel(const float* __restrict__ W,
                                                     __half* __restrict__ wp) {
    const int e = blockIdx.z, nt = blockIdx.y, kb = blockIdx.x;
    const float* Wt = W + ((size_t)e * KD + kb * 32) * ND + nt * 128;
    uint2* op = (uint2*)(wp + (((size_t)e * NT_ + nt) * KIT_ + kb) * 4096);
    const int tid = threadIdx.x;
#pragma unroll
    for (int p = 0; p < 4; p++) {
        int G = tid + p * 256;               // 0..1023
        int s = G >> 9;
        int r = G & 511;
        int n = (r >> 5) * 8 + ((r & 31) >> 2);
        int t = r & 3;
        int k0 = s * 16 + 2 * t;
        float f0 = Wt[(size_t)(k0    ) * ND + n];
        float f1 = Wt[(size_t)(k0 + 1) * ND + n];
        float f2 = Wt[(size_t)(k0 + 8) * ND + n];
        float f3 = Wt[(size_t)(k0 + 9) * ND + n];
        __half2 h0 = __floats2half2_rn(f0, f1);
        __half2 h1 = __floats2half2_rn(f2, f3);
        uint2 u;
        u.x = *(uint32_t*)&h0;
        u.y = *(uint32_t*)&h1;
        op[G] = u;
    }
}

// ---------------------------------------------------------------------------
// GEMM. G1: h = gelu(x@W1 + b1) -> g_h (fp16, k-permuted).
//       G2: g_y[slot][tok] = gw * (h@W2 + b2).
// R8-form COMPUTE (per-k16 fragment loads); inline padded-prefix offsets.
// ---------------------------------------------------------------------------
template <bool G1, int KDIM, int NDIM, int NT_>
__global__ __launch_bounds__(128, 2) void moe_gemm_kernel(
    const __half* __restrict__ Bpack,
    const float* __restrict__ bias)
{
    const int e = blockIdx.z;
    int off = 0, cnt = 0;
#pragma unroll
    for (int i = 0; i < NEXP; i++) {
        int c = g_cnt[i];
        if (i == e) cnt = c;
        if (i < e) off += (c + 127) & ~127;
    }
    const int mt = blockIdx.y;
    if (mt * BM >= cnt) return;
    const int nt = blockIdx.x;

    extern __shared__ char smem[];
    const uint32_t sA = smem_u32(smem);
    const uint32_t sB = sA + SMEM_B_OFF;
    int*   sTok = (int*)(smem + SMEM_TOK_OFF);
    float* sW   = (float*)(smem + SMEM_W_OFF);

    const int tid  = threadIdx.x;
    const int warp = tid >> 5, lane = tid & 31;
    const int wm = warp >> 1, wn = warp & 1;
    const int gid = lane >> 2, tig = lane & 3;

    if (tid < BM) {
        int slot = mt * BM + tid;
        sTok[tid] = (slot < cnt) ? g_tok[e * NTOK + slot] : -1;
        sW[tid]   = (slot < cnt) ? g_gw [e * NTOK + slot] : 0.f;
    }
    __syncthreads();

    const int hrow0 = off + mt * BM;
    constexpr int KIT = KDIM / BK;

    const __half* srcA[4];
    uint32_t dstA[4], szA[4];
    const int kq = tid & 3;
#pragma unroll
    for (int c = 0; c < 4; c++) {
        int r = (tid >> 2) + c * 32;
        dstA[c] = r * APITCH + kq * 16;
        if constexpr (G1) {
            int tkr = sTok[r];
            int tk  = tkr >> 1;
            srcA[c] = g_x + (size_t)(tkr >= 0 ? tk : 0) * DIM + kq * 8;
            szA[c]  = (tkr >= 0) ? 16u : 0u;
        } else {
            srcA[c] = g_h + (size_t)(hrow0 + r) * KDIM + kq * 8;
            szA[c]  = 16u;
        }
    }
    const __half* srcB = Bpack + (((size_t)e * NT_ + nt) * KIT) * 4096 + tid * 8;

    float acc[4][8][4];
#pragma unroll
    for (int mi = 0; mi < 4; mi++)
#pragma unroll
        for (int ni = 0; ni < 8; ni++)
#pragma unroll
            for (int r = 0; r < 4; r++) acc[mi][ni][r] = 0.f;

    auto FILL = [&](int it, int buf) {
        const uint32_t aB = sA + buf * A_STAGE_BYTES;
        const uint32_t bB = sB + buf * B_STAGE_BYTES;
        const int koff = it * BK;
#pragma unroll
        for (int c = 0; c < 4; c++)
            CP16Z(aB + dstA[c], srcA[c] + koff, szA[c]);
        const __half* bsrc = srcB + (size_t)it * 4096;
#pragma unroll
        for (int c = 0; c < 4; c++)
            CP16(bB + (tid + c * 128) * 16, bsrc + c * 1024);
    };

    auto COMPUTE = [&](int buf) {
        const uint32_t aB = sA + buf * A_STAGE_BYTES;
        const uint32_t bB = sB + buf * B_STAGE_BYTES;
#pragma unroll
        for (int k16 = 0; k16 < 2; k16++) {
            uint32_t af[4][4], bf[8][2];
#pragma unroll
            for (int mi = 0; mi < 4; mi++) {
                uint32_t ad = aB + (wm * 64 + mi * 16 + gid) * APITCH + k16 * 32 + tig * 8;
                asm("ld.shared.v2.b32 {%0,%1},[%2];"
                    : "=r"(af[mi][0]), "=r"(af[mi][2]) : "r"(ad));
                asm("ld.shared.v2.b32 {%0,%1},[%2];"
                    : "=r"(af[mi][1]), "=r"(af[mi][3]) : "r"(ad + 8 * APITCH));
            }
#pragma unroll
            for (int ni = 0; ni < 8; ni++) {
                uint32_t bd = bB + k16 * 4096 + (wn * 8 + ni) * 256 + lane * 8;
                asm("ld.shared.v2.b32 {%0,%1},[%2];"
                    : "=r"(bf[ni][0]), "=r"(bf[ni][1]) : "r"(bd));
            }
#pragma unroll
            for (int mi = 0; mi < 4; mi++)
#pragma unroll
                for (int ni = 0; ni < 8; ni++)
                    mma_f16(acc[mi][ni], af[mi], bf[ni]);
        }
    };

#pragma unroll
    for (int s = 0; s < STAGES - 1; s++) { FILL(s, s); CP_COMMIT(); }

#pragma unroll 1
    for (int it = 0; it < KIT; ++it) {
        CP_WAIT(2);
        __syncthreads();
        COMPUTE(it & (STAGES - 1));
        int nf = it + STAGES - 1;
        if (nf < KIT) FILL(nf, nf & (STAGES - 1));
        CP_COMMIT();
    }
    __syncthreads();    // pipeline drained; smem reusable

    // ---- epilogue via SMEM bounce; lane-major coalesced global stores
    if constexpr (G1) {
        __half* sH = (__half*)smem;          // 128 rows x 136 halfs
#pragma unroll
        for (int mi = 0; mi < 4; mi++) {
#pragma unroll
            for (int ni = 0; ni < 8; ni++) {
                int Lb = wn * 64 + ni * 8 + tig * 2;
                float b0 = bias[e * NDIM + nt * BN + Lb];
                float b1 = bias[e * NDIM + nt * BN + Lb + 1];
                int pos = (Lb & ~15) + permh(Lb & 15);
#pragma unroll
                for (int h = 0; h < 2; h++) {
                    int row = wm * 64 + mi * 16 + gid + h * 8;
                    float vx = acc[mi][ni][h * 2 + 0] + b0;
                    float vy = acc[mi][ni][h * 2 + 1] + b1;
                    vx = 0.5f * vx * (1.f + erff(vx * 0.70710678118654752f));
                    vy = 0.5f * vy * (1.f + erff(vy * 0.70710678118654752f));
                    *(__half2*)(sH + row * 136 + pos) = __floats2half2_rn(vx, vy);
                }
            }
        }
        __syncthreads();
#pragma unroll
        for (int i = 0; i < 16; i++) {
            int idx = tid + i * 128;
            int row = idx >> 4, c = idx & 15;
            ((uint4*)(g_h + (size_t)(hrow0 + row) * NDIM + nt * BN))[c]
                = ((const uint4*)(sH + row * 136))[c];
        }
    } else {
        float* sO = (float*)smem;            // 128 rows x 132 words
#pragma unroll
        for (int mi = 0; mi < 4; mi++) {
#pragma unroll
            for (int ni = 0; ni < 8; ni++) {
                int Lb = wn * 64 + ni * 8 + tig * 2;
                float b0 = bias[e * NDIM + nt * BN + Lb];
                float b1 = bias[e * NDIM + nt * BN + Lb + 1];
#pragma unroll
                for (int h = 0; h < 2; h++) {
                    int row = wm * 64 + mi * 16 + gid + h * 8;
                    float w = sW[row];
                    float vx = (acc[mi][ni][h * 2 + 0] + b0) * w;
                    float vy = (acc[mi][ni][h * 2 + 1] + b1) * w;
                    *(float2*)(sO + row * 132 + Lb) = make_float2(vx, vy);
                }
            }
        }
        __syncthreads();
#pragma unroll
        for (int i = 0; i < 32; i++) {
            int idx = tid + i * 128;
            int row = idx >> 5, c = idx & 31;
            int tkr = sTok[row];
            if (tkr >= 0) {
                ((float4*)(g_y + ((size_t)(tkr & 1) * NTOK + (tkr >> 1)) * DIM + nt * BN))[c]
                    = ((const float4*)(sO + row * 132))[c];
            }
        }
    }
}

// ---------------------------------------------------------------------------
// Combine: out = y0 + y1
// ---------------------------------------------------------------------------
__global__ __launch_bounds__(256) void combine_kernel(float4* __restrict__ out4) {
    int i = blockIdx.x * 256 + threadIdx.x;
    if (i >= NTOK * DIM / 4) return;
    const float4 a = ((const float4*)g_y)[i];
    const float4 b = ((const float4*)g_y)[i + NTOK * DIM / 4];
    out4[i] = make_float4(a.x + b.x, a.y + b.y, a.z + b.z, a.w + b.w);
}

// ---------------------------------------------------------------------------
namespace {
cudaStream_t s1, s2, s3;
cudaEvent_t  evF, ev1, ev2, ev3;
struct ModuleWarmup {
    ModuleWarmup() {
        void* p = nullptr;
        (void)cudaGetSymbolAddress(&p, g_h);
        (void)cudaGetSymbolAddress(&p, g_w1p);
        (void)cudaGetSymbolAddress(&p, g_w2p);
        (void)cudaGetSymbolAddress(&p, g_x);
        (void)cudaGetSymbolAddress(&p, g_y);
        cudaStreamCreateWithFlags(&s1, cudaStreamNonBlocking);
        cudaStreamCreateWithFlags(&s2, cudaStreamNonBlocking);
        cudaStreamCreateWithFlags(&s3, cudaStreamNonBlocking);
        cudaEventCreateWithFlags(&evF, cudaEventDisableTiming);
        cudaEventCreateWithFlags(&ev1, cudaEventDisableTiming);
        cudaEventCreateWithFlags(&ev2, cudaEventDisableTiming);
        cudaEventCreateWithFlags(&ev3, cudaEventDisableTiming);
    }
};
ModuleWarmup g_module_warmup;
}

extern "C" void kernel_launch(void* const* d_in, const int* in_sizes, int n_in,
                              void* d_out, int out_size) {
    const float* x  = (const float*)d_in[0];   // [2,2048,1024]
    const float* Wr = (const float*)d_in[1];   // [1024,8]
    const float* W1 = (const float*)d_in[2];   // [8,1024,4096]
    const float* b1 = (const float*)d_in[3];   // [8,4096]
    const float* W2 = (const float*)d_in[4];   // [8,4096,1024]
    const float* b2 = (const float*)d_in[5];   // [8,1024]
    float* out = (float*)d_out;                // [2,2048,1024]

    __half *w1p = nullptr, *w2p = nullptr;
    int* cntp = nullptr;
    cudaGetSymbolAddress((void**)&w1p, g_w1p);
    cudaGetSymbolAddress((void**)&w2p, g_w2p);
    cudaGetSymbolAddress((void**)&cntp, g_cnt);

    cudaFuncSetAttribute(moe_gemm_kernel<true,  DIM,  FDIM, 32>,
                         cudaFuncAttributeMaxDynamicSharedMemorySize, SMEM_TOTAL);
    cudaFuncSetAttribute(moe_gemm_kernel<false, FDIM, DIM, 8>,
                         cudaFuncAttributeMaxDynamicSharedMemorySize, SMEM_TOTAL);

    // fork: conv_x / conv_w1 / conv_w2 on side streams; router chain on s0
    cudaMemsetAsync(cntp, 0, sizeof(int) * NEXP, 0);
    cudaEventRecord(evF, 0);
    cudaStreamWaitEvent(s1, evF, 0);
    cudaStreamWaitEvent(s2, evF, 0);
    cudaStreamWaitEvent(s3, evF, 0);

    conv_x_kernel<<<(NTOK * DIM / 8 + 255) / 256, 256, 0, s1>>>(x);
    cudaEventRecord(ev1, s1);
    conv_w_kernel<DIM,  FDIM, 32, 32 ><<<dim3(32,  32, NEXP), 256, 0, s2>>>(W1, w1p);
    cudaEventRecord(ev2, s2);
    conv_w_kernel<FDIM, DIM,  8,  128><<<dim3(128, 8,  NEXP), 256, 0, s3>>>(W2, w2p);
    cudaEventRecord(ev3, s3);

    router_kernel<<<NTOK / 8, 256>>>(x, Wr);

    // G1 needs conv_x + conv_w1 + router; conv_w2 keeps streaming underneath G1
    cudaStreamWaitEvent(0, ev1, 0);
    cudaStreamWaitEvent(0, ev2, 0);
    {
        dim3 grid(FDIM / BN, NTOK / BM, NEXP);   // (32, 32, 8)
        moe_gemm_kernel<true, DIM, FDIM, 32><<<grid, 128, SMEM_TOTAL>>>(w1p, b1);
    }
    cudaStreamWaitEvent(0, ev3, 0);
    {
        dim3 grid(DIM / BN, NTOK / BM, NEXP);    // (8, 32, 8)
        moe_gemm_kernel<false, FDIM, DIM, 8><<<grid, 128, SMEM_TOTAL>>>(w2p, b2);
    }
    combine_kernel<<<(NTOK * DIM / 4 + 255) / 256, 256>>>((float4*)out);
}